// round 1
// baseline (speedup 1.0000x reference)
#include <cuda_runtime.h>
#include <math.h>

// Problem constants
constexpr int Bb  = 2;
constexpr int Nn  = 2048;
constexpr int Dd  = 1024;
constexpr int Hh  = 16;
constexpr int DHh = 64;
constexpr int D3  = 3 * Dd;   // 3072

// Scratch (allocation-free rule: __device__ globals)
__device__ float g_qkv[Bb * Nn * D3];    // [B,N,3*H*DH]
__device__ float g_attn[Bb * Nn * Dd];   // [B,N,H*DH]

// ---------------------------------------------------------------------------
// C[M,N] = A[M,K] @ B[N,K]^T + bias[N]
// A row-major [M,K], B row-major [N,K] (so both K-contiguous -> NT gemm).
// 128x128 block tile, BK=8, 256 threads, 8x8 per-thread tile,
// register-prefetch pipeline.
// Requires M%128==0, N%128==0, K%8==0.
// ---------------------------------------------------------------------------
__global__ __launch_bounds__(256) void sgemm_nt_bias(
    const float* __restrict__ A, const float* __restrict__ B,
    const float* __restrict__ bias, float* __restrict__ C,
    int M, int N, int K)
{
    __shared__ float As[8][132];   // k-major, padded (132*4B row = 528B, 16B-mult)
    __shared__ float Bs[8][132];

    const int tid = threadIdx.x;
    const int m0 = blockIdx.y * 128;
    const int n0 = blockIdx.x * 128;

    const int lr = tid >> 1;           // 0..127 (row within tile)
    const int lc = (tid & 1) * 4;      // 0 or 4 (k offset)

    const float* Ag = A + (size_t)(m0 + lr) * K + lc;
    const float* Bg = B + (size_t)(n0 + lr) * K + lc;

    const int tx = tid & 15;           // 0..15 -> n direction
    const int ty = tid >> 4;           // 0..15 -> m direction

    float acc[8][8];
    #pragma unroll
    for (int i = 0; i < 8; i++)
        #pragma unroll
        for (int j = 0; j < 8; j++) acc[i][j] = 0.f;

    float4 ra = *(const float4*)Ag;
    float4 rb = *(const float4*)Bg;

    const int kt_total = K / 8;
    for (int kt = 0;;) {
        // stage current tile into smem (transposed: As[k][m])
        As[lc + 0][lr] = ra.x; As[lc + 1][lr] = ra.y;
        As[lc + 2][lr] = ra.z; As[lc + 3][lr] = ra.w;
        Bs[lc + 0][lr] = rb.x; Bs[lc + 1][lr] = rb.y;
        Bs[lc + 2][lr] = rb.z; Bs[lc + 3][lr] = rb.w;
        __syncthreads();

        ++kt;
        if (kt < kt_total) {           // prefetch next tile during compute
            Ag += 8; Bg += 8;
            ra = *(const float4*)Ag;
            rb = *(const float4*)Bg;
        }

        #pragma unroll
        for (int k = 0; k < 8; k++) {
            float a[8], b[8];
            *(float4*)(a)     = *(const float4*)&As[k][ty * 8];
            *(float4*)(a + 4) = *(const float4*)&As[k][ty * 8 + 4];
            *(float4*)(b)     = *(const float4*)&Bs[k][tx * 8];
            *(float4*)(b + 4) = *(const float4*)&Bs[k][tx * 8 + 4];
            #pragma unroll
            for (int i = 0; i < 8; i++)
                #pragma unroll
                for (int j = 0; j < 8; j++)
                    acc[i][j] = fmaf(a[i], b[j], acc[i][j]);
        }

        if (kt >= kt_total) break;
        __syncthreads();
    }

    // epilogue: add bias, write out
    float bv[8];
    *(float4*)(bv)     = *(const float4*)&bias[n0 + tx * 8];
    *(float4*)(bv + 4) = *(const float4*)&bias[n0 + tx * 8 + 4];
    #pragma unroll
    for (int i = 0; i < 8; i++) {
        float* Crow = C + (size_t)(m0 + ty * 8 + i) * N + n0 + tx * 8;
        float4 v0 = make_float4(acc[i][0] + bv[0], acc[i][1] + bv[1],
                                acc[i][2] + bv[2], acc[i][3] + bv[3]);
        float4 v1 = make_float4(acc[i][4] + bv[4], acc[i][5] + bv[5],
                                acc[i][6] + bv[6], acc[i][7] + bv[7]);
        *(float4*)(Crow)     = v0;
        *(float4*)(Crow + 4) = v1;
    }
}

// ---------------------------------------------------------------------------
// Flash attention, fp32, online softmax.
// Grid: (N/64, H, B). Block: 256 threads.
// Warp w owns query rows w*8 .. w*8+7 within the 64-row tile.
// Within a row, 4 lanes each own a 16-wide DH slice (quarter = lane%4).
// K/V tiles of 64 keys staged in smem; S processed in 16-key sub-chunks
// kept in registers; cross-lane dot reduction via shfl_xor within 4-lane
// groups (after which all 4 lanes hold identical full dot products, so
// m/l softmax state stays bit-identical across the row's lanes).
// ---------------------------------------------------------------------------
__global__ __launch_bounds__(256) void flash_attn(
    const float* __restrict__ qkv, float* __restrict__ out)
{
    __shared__ float Ks[64][68];   // 68*4B = 272B row, 16B-multiple
    __shared__ float Vs[64][68];

    const int tid     = threadIdx.x;
    const int lane    = tid & 31;
    const int w       = tid >> 5;
    const int quarter = lane & 3;          // DH slice owner
    const int r       = w * 8 + (lane >> 2);  // query row in tile (0..63)

    const int qt = blockIdx.x;
    const int h  = blockIdx.y;
    const int b  = blockIdx.z;
    const int qg = qt * 64 + r;            // global query row

    // load q (scaled by DH^-0.5 = 0.125)
    const float* qbase = qkv + ((size_t)(b * Nn + qg)) * D3 + h * DHh + quarter * 16;
    float q[16];
    #pragma unroll
    for (int i = 0; i < 16; i += 4) {
        float4 t = *(const float4*)(qbase + i);
        q[i] = t.x * 0.125f; q[i + 1] = t.y * 0.125f;
        q[i + 2] = t.z * 0.125f; q[i + 3] = t.w * 0.125f;
    }

    float o[16];
    #pragma unroll
    for (int i = 0; i < 16; i++) o[i] = 0.f;
    float m = -1e30f, l = 0.f;

    // cooperative K/V tile load mapping: thread -> (row, 16-float segment)
    const int lrow = tid >> 2;
    const int lseg = (tid & 3) * 16;

    for (int t = 0; t < Nn / 64; t++) {
        const float* kb = qkv + ((size_t)(b * Nn + t * 64 + lrow)) * D3
                        + Dd + h * DHh + lseg;          // K block at col 1024
        const float* vb = kb + Dd;                       // V block at col 2048
        __syncthreads();   // previous tile fully consumed
        #pragma unroll
        for (int i = 0; i < 16; i += 4) {
            *(float4*)&Ks[lrow][lseg + i] = *(const float4*)(kb + i);
            *(float4*)&Vs[lrow][lseg + i] = *(const float4*)(vb + i);
        }
        __syncthreads();

        #pragma unroll
        for (int c = 0; c < 4; c++) {      // 16-key sub-chunks
            float s[16];
            #pragma unroll
            for (int j = 0; j < 16; j++) {
                const float* kr = &Ks[c * 16 + j][quarter * 16];
                float acc = 0.f;
                #pragma unroll
                for (int i = 0; i < 16; i += 4) {
                    float4 k4 = *(const float4*)(kr + i);
                    acc = fmaf(q[i], k4.x, acc);
                    acc = fmaf(q[i + 1], k4.y, acc);
                    acc = fmaf(q[i + 2], k4.z, acc);
                    acc = fmaf(q[i + 3], k4.w, acc);
                }
                s[j] = acc;
            }
            // reduce partial dots across the 4 lanes of this row
            #pragma unroll
            for (int j = 0; j < 16; j++) {
                s[j] += __shfl_xor_sync(0xffffffffu, s[j], 1);
                s[j] += __shfl_xor_sync(0xffffffffu, s[j], 2);
            }
            // online softmax update (identical across the row's 4 lanes)
            float mc = s[0];
            #pragma unroll
            for (int j = 1; j < 16; j++) mc = fmaxf(mc, s[j]);
            float mn   = fmaxf(m, mc);
            float corr = __expf(m - mn);
            float p[16], ps = 0.f;
            #pragma unroll
            for (int j = 0; j < 16; j++) { p[j] = __expf(s[j] - mn); ps += p[j]; }
            l = l * corr + ps;
            m = mn;
            #pragma unroll
            for (int i = 0; i < 16; i++) o[i] *= corr;
            #pragma unroll
            for (int j = 0; j < 16; j++) {
                const float* vr = &Vs[c * 16 + j][quarter * 16];
                #pragma unroll
                for (int i = 0; i < 16; i += 4) {
                    float4 v4 = *(const float4*)(vr + i);
                    o[i]     = fmaf(p[j], v4.x, o[i]);
                    o[i + 1] = fmaf(p[j], v4.y, o[i + 1]);
                    o[i + 2] = fmaf(p[j], v4.z, o[i + 2]);
                    o[i + 3] = fmaf(p[j], v4.w, o[i + 3]);
                }
            }
        }
    }

    const float inv = 1.f / l;
    float* ob = out + ((size_t)(b * Nn + qg)) * Dd + h * DHh + quarter * 16;
    #pragma unroll
    for (int i = 0; i < 16; i += 4) {
        float4 v = make_float4(o[i] * inv, o[i + 1] * inv,
                               o[i + 2] * inv, o[i + 3] * inv);
        *(float4*)(ob + i) = v;
    }
}

// ---------------------------------------------------------------------------
// Host launcher
// ---------------------------------------------------------------------------
extern "C" void kernel_launch(void* const* d_in, const int* in_sizes, int n_in,
                              void* d_out, int out_size)
{
    const float* x     = (const float*)d_in[0];   // [B,N,D]
    const float* W_w   = (const float*)d_in[1];   // [3*H*DH, D]
    const float* W_b   = (const float*)d_in[2];   // [3*H*DH]
    const float* out_w = (const float*)d_in[3];   // [D, H*DH]
    const float* out_b = (const float*)d_in[4];   // [D]

    float* qkv  = nullptr;
    float* attn = nullptr;
    cudaGetSymbolAddress((void**)&qkv,  g_qkv);
    cudaGetSymbolAddress((void**)&attn, g_attn);

    const int M = Bb * Nn;   // 4096

    // qkv = x @ W_w^T + W_b     [4096, 3072]
    sgemm_nt_bias<<<dim3(D3 / 128, M / 128), 256>>>(x, W_w, W_b, qkv, M, D3, Dd);

    // attention -> attn [B,N,H*DH]
    flash_attn<<<dim3(Nn / 64, Hh, Bb), 256>>>(qkv, attn);

    // out = attn @ out_w^T + out_b   [4096, 1024]
    sgemm_nt_bias<<<dim3(Dd / 128, M / 128), 256>>>(attn, out_w, out_b,
                                                    (float*)d_out, M, Dd, Dd);
}

// round 2
// speedup vs baseline: 3.7925x; 3.7925x over previous
#include <cuda_runtime.h>
#include <math.h>
#include <stdint.h>

// Problem constants
constexpr int Bb  = 2;
constexpr int Nn  = 2048;
constexpr int Dd  = 1024;
constexpr int Hh  = 16;
constexpr int DHh = 64;
constexpr int D3  = 3 * Dd;   // 3072

// Scratch (allocation-free rule: __device__ globals)
__device__ float g_qkv[Bb * Nn * D3];    // [B,N,3*H*DH]
__device__ float g_attn[Bb * Nn * Dd];   // [B,N,H*DH]

// ---------------------------------------------------------------------------
// helpers
// ---------------------------------------------------------------------------
__device__ __forceinline__ uint32_t f2tf32(float x) {
    uint32_t r;
    asm("cvt.rna.tf32.f32 %0, %1;" : "=r"(r) : "f"(x));
    return r;
}

__device__ __forceinline__ void mma_tf32(
    float& c0, float& c1, float& c2, float& c3,
    uint32_t a0, uint32_t a1, uint32_t a2, uint32_t a3,
    uint32_t b0, uint32_t b1)
{
    asm volatile(
        "mma.sync.aligned.m16n8k8.row.col.f32.tf32.tf32.f32 "
        "{%0,%1,%2,%3}, {%4,%5,%6,%7}, {%8,%9}, {%0,%1,%2,%3};\n"
        : "+f"(c0), "+f"(c1), "+f"(c2), "+f"(c3)
        : "r"(a0), "r"(a1), "r"(a2), "r"(a3), "r"(b0), "r"(b1));
}

// ---------------------------------------------------------------------------
// C[M,N] = A[M,K] @ B[N,K]^T + bias[N]   (fp32, unchanged from R1)
// ---------------------------------------------------------------------------
__global__ __launch_bounds__(256) void sgemm_nt_bias(
    const float* __restrict__ A, const float* __restrict__ B,
    const float* __restrict__ bias, float* __restrict__ C,
    int M, int N, int K)
{
    __shared__ float As[8][132];
    __shared__ float Bs[8][132];

    const int tid = threadIdx.x;
    const int m0 = blockIdx.y * 128;
    const int n0 = blockIdx.x * 128;

    const int lr = tid >> 1;
    const int lc = (tid & 1) * 4;

    const float* Ag = A + (size_t)(m0 + lr) * K + lc;
    const float* Bg = B + (size_t)(n0 + lr) * K + lc;

    const int tx = tid & 15;
    const int ty = tid >> 4;

    float acc[8][8];
    #pragma unroll
    for (int i = 0; i < 8; i++)
        #pragma unroll
        for (int j = 0; j < 8; j++) acc[i][j] = 0.f;

    float4 ra = *(const float4*)Ag;
    float4 rb = *(const float4*)Bg;

    const int kt_total = K / 8;
    for (int kt = 0;;) {
        As[lc + 0][lr] = ra.x; As[lc + 1][lr] = ra.y;
        As[lc + 2][lr] = ra.z; As[lc + 3][lr] = ra.w;
        Bs[lc + 0][lr] = rb.x; Bs[lc + 1][lr] = rb.y;
        Bs[lc + 2][lr] = rb.z; Bs[lc + 3][lr] = rb.w;
        __syncthreads();

        ++kt;
        if (kt < kt_total) {
            Ag += 8; Bg += 8;
            ra = *(const float4*)Ag;
            rb = *(const float4*)Bg;
        }

        #pragma unroll
        for (int k = 0; k < 8; k++) {
            float a[8], b[8];
            *(float4*)(a)     = *(const float4*)&As[k][ty * 8];
            *(float4*)(a + 4) = *(const float4*)&As[k][ty * 8 + 4];
            *(float4*)(b)     = *(const float4*)&Bs[k][tx * 8];
            *(float4*)(b + 4) = *(const float4*)&Bs[k][tx * 8 + 4];
            #pragma unroll
            for (int i = 0; i < 8; i++)
                #pragma unroll
                for (int j = 0; j < 8; j++)
                    acc[i][j] = fmaf(a[i], b[j], acc[i][j]);
        }

        if (kt >= kt_total) break;
        __syncthreads();
    }

    float bv[8];
    *(float4*)(bv)     = *(const float4*)&bias[n0 + tx * 8];
    *(float4*)(bv + 4) = *(const float4*)&bias[n0 + tx * 8 + 4];
    #pragma unroll
    for (int i = 0; i < 8; i++) {
        float* Crow = C + (size_t)(m0 + ty * 8 + i) * N + n0 + tx * 8;
        float4 v0 = make_float4(acc[i][0] + bv[0], acc[i][1] + bv[1],
                                acc[i][2] + bv[2], acc[i][3] + bv[3]);
        float4 v1 = make_float4(acc[i][4] + bv[4], acc[i][5] + bv[5],
                                acc[i][6] + bv[6], acc[i][7] + bv[7]);
        *(float4*)(Crow)     = v0;
        *(float4*)(Crow + 4) = v1;
    }
}

// ---------------------------------------------------------------------------
// Flash attention on tensor cores (tf32 mma.sync), online softmax.
// Grid: (N/128, H, B), Block: 256 (8 warps).
// Warp w owns query rows w*16 .. w*16+15 of a 128-query tile.
// K/V tiles of 64 keys in smem (tf32 bits, conflict-free pads).
// S and O live in m16n8k8 C-fragments; P transposed C->A layout via
// quad shuffles (no smem roundtrip).
// ---------------------------------------------------------------------------
__global__ __launch_bounds__(256, 1) void flash_attn_mma(
    const float* __restrict__ qkv, float* __restrict__ out)
{
    constexpr int KS = 68;   // K tile row stride (floats): banks 4*qr+qc, conflict-free
    constexpr int VS = 72;   // V tile row stride: banks 8*qc+qr, conflict-free
    __shared__ float Ks[64 * KS];
    __shared__ float Vs[64 * VS];

    const int tid  = threadIdx.x;
    const int lane = tid & 31;
    const int w    = tid >> 5;
    const int qr   = lane >> 2;   // group id (row within frag)
    const int qc   = lane & 3;    // thread-in-group
    const int h    = blockIdx.y;
    const int b    = blockIdx.z;
    const int q0   = blockIdx.x * 128;
    const int row0 = w * 16;

    // ---- load Q into A-fragments (scaled by DH^-0.5), once ----
    uint32_t Qa[8][4];
    {
        const float* qb    = qkv + ((size_t)(b * Nn + q0)) * D3 + h * DHh;
        const float* qrow0 = qb + (size_t)(row0 + qr) * D3;
        const float* qrow1 = qb + (size_t)(row0 + qr + 8) * D3;
        #pragma unroll
        for (int k = 0; k < 8; k++) {
            Qa[k][0] = f2tf32(qrow0[k * 8 + qc]     * 0.125f);
            Qa[k][1] = f2tf32(qrow1[k * 8 + qc]     * 0.125f);
            Qa[k][2] = f2tf32(qrow0[k * 8 + qc + 4] * 0.125f);
            Qa[k][3] = f2tf32(qrow1[k * 8 + qc + 4] * 0.125f);
        }
    }

    float O[8][4];
    #pragma unroll
    for (int nt = 0; nt < 8; nt++)
        #pragma unroll
        for (int i = 0; i < 4; i++) O[nt][i] = 0.f;
    float mA = -1e30f, mB = -1e30f, lA = 0.f, lB = 0.f;

    // cooperative K/V tile load mapping
    const int lrow = tid >> 2;
    const int lseg = (tid & 3) * 16;

    for (int t = 0; t < Nn / 64; t++) {
        const float* kb = qkv + ((size_t)(b * Nn + t * 64 + lrow)) * D3
                        + Dd + h * DHh + lseg;
        const float* vb = kb + Dd;
        __syncthreads();   // previous tile fully consumed
        #pragma unroll
        for (int i = 0; i < 16; i += 4) {
            float4 kv = *(const float4*)(kb + i);
            float4 vv = *(const float4*)(vb + i);
            float* kd = &Ks[lrow * KS + lseg + i];
            float* vd = &Vs[lrow * VS + lseg + i];
            kd[0] = __uint_as_float(f2tf32(kv.x));
            kd[1] = __uint_as_float(f2tf32(kv.y));
            kd[2] = __uint_as_float(f2tf32(kv.z));
            kd[3] = __uint_as_float(f2tf32(kv.w));
            vd[0] = __uint_as_float(f2tf32(vv.x));
            vd[1] = __uint_as_float(f2tf32(vv.y));
            vd[2] = __uint_as_float(f2tf32(vv.z));
            vd[3] = __uint_as_float(f2tf32(vv.w));
        }
        __syncthreads();

        // ---- S = Q @ K^T : 8 n-tiles of 8 keys, k = 64 (8 mma steps) ----
        float S[8][4];
        #pragma unroll
        for (int nt = 0; nt < 8; nt++) {
            float c0 = 0.f, c1 = 0.f, c2 = 0.f, c3 = 0.f;
            const float* kbase = &Ks[(nt * 8 + qr) * KS + qc];
            #pragma unroll
            for (int k = 0; k < 8; k++) {
                uint32_t b0 = __float_as_uint(kbase[k * 8]);
                uint32_t b1 = __float_as_uint(kbase[k * 8 + 4]);
                mma_tf32(c0, c1, c2, c3,
                         Qa[k][0], Qa[k][1], Qa[k][2], Qa[k][3], b0, b1);
            }
            S[nt][0] = c0; S[nt][1] = c1; S[nt][2] = c2; S[nt][3] = c3;
        }

        // ---- online softmax: row max over 64 cols (quad reduce) ----
        float cmA = -1e30f, cmB = -1e30f;
        #pragma unroll
        for (int nt = 0; nt < 8; nt++) {
            cmA = fmaxf(cmA, fmaxf(S[nt][0], S[nt][1]));
            cmB = fmaxf(cmB, fmaxf(S[nt][2], S[nt][3]));
        }
        cmA = fmaxf(cmA, __shfl_xor_sync(0xffffffffu, cmA, 1));
        cmA = fmaxf(cmA, __shfl_xor_sync(0xffffffffu, cmA, 2));
        cmB = fmaxf(cmB, __shfl_xor_sync(0xffffffffu, cmB, 1));
        cmB = fmaxf(cmB, __shfl_xor_sync(0xffffffffu, cmB, 2));

        const float mnA = fmaxf(mA, cmA), mnB = fmaxf(mB, cmB);
        const float corrA = __expf(mA - mnA), corrB = __expf(mB - mnB);
        #pragma unroll
        for (int nt = 0; nt < 8; nt++) {
            O[nt][0] *= corrA; O[nt][1] *= corrA;
            O[nt][2] *= corrB; O[nt][3] *= corrB;
        }

        // ---- P = exp(S - mn); transpose C-layout -> A-layout via quad
        //      shuffles; O += P @ V ----
        float psA = 0.f, psB = 0.f;
        const int quadbase = lane & ~3;
        const int s0l = quadbase | (qc >> 1);
        const int s1l = s0l + 2;
        const bool odd = qc & 1;
        #pragma unroll
        for (int ks = 0; ks < 8; ks++) {
            float p0 = __expf(S[ks][0] - mnA);
            float p1 = __expf(S[ks][1] - mnA);
            float p2 = __expf(S[ks][2] - mnB);
            float p3 = __expf(S[ks][3] - mnB);
            psA += p0 + p1;
            psB += p2 + p3;

            float g00 = __shfl_sync(0xffffffffu, p0, s0l);
            float g01 = __shfl_sync(0xffffffffu, p1, s0l);
            float g20 = __shfl_sync(0xffffffffu, p2, s0l);
            float g21 = __shfl_sync(0xffffffffu, p3, s0l);
            float h00 = __shfl_sync(0xffffffffu, p0, s1l);
            float h01 = __shfl_sync(0xffffffffu, p1, s1l);
            float h20 = __shfl_sync(0xffffffffu, p2, s1l);
            float h21 = __shfl_sync(0xffffffffu, p3, s1l);

            uint32_t a0 = f2tf32(odd ? g01 : g00);
            uint32_t a1 = f2tf32(odd ? g21 : g20);
            uint32_t a2 = f2tf32(odd ? h01 : h00);
            uint32_t a3 = f2tf32(odd ? h21 : h20);

            const float* vbase = &Vs[(ks * 8 + qc) * VS + qr];
            #pragma unroll
            for (int nt = 0; nt < 8; nt++) {
                uint32_t b0 = __float_as_uint(vbase[nt * 8]);
                uint32_t b1 = __float_as_uint(vbase[nt * 8 + 4 * VS]);
                mma_tf32(O[nt][0], O[nt][1], O[nt][2], O[nt][3],
                         a0, a1, a2, a3, b0, b1);
            }
        }
        psA += __shfl_xor_sync(0xffffffffu, psA, 1);
        psA += __shfl_xor_sync(0xffffffffu, psA, 2);
        psB += __shfl_xor_sync(0xffffffffu, psB, 1);
        psB += __shfl_xor_sync(0xffffffffu, psB, 2);
        lA = lA * corrA + psA; mA = mnA;
        lB = lB * corrB + psB; mB = mnB;
    }

    // ---- epilogue ----
    const float invA = 1.f / lA, invB = 1.f / lB;
    float* ob    = out + ((size_t)(b * Nn + q0)) * Dd + h * DHh;
    float* orow0 = ob + (size_t)(row0 + qr) * Dd;
    float* orow1 = ob + (size_t)(row0 + qr + 8) * Dd;
    #pragma unroll
    for (int nt = 0; nt < 8; nt++) {
        int c = nt * 8 + qc * 2;
        *(float2*)&orow0[c] = make_float2(O[nt][0] * invA, O[nt][1] * invA);
        *(float2*)&orow1[c] = make_float2(O[nt][2] * invB, O[nt][3] * invB);
    }
}

// ---------------------------------------------------------------------------
// Host launcher
// ---------------------------------------------------------------------------
extern "C" void kernel_launch(void* const* d_in, const int* in_sizes, int n_in,
                              void* d_out, int out_size)
{
    const float* x     = (const float*)d_in[0];   // [B,N,D]
    const float* W_w   = (const float*)d_in[1];   // [3*H*DH, D]
    const float* W_b   = (const float*)d_in[2];   // [3*H*DH]
    const float* out_w = (const float*)d_in[3];   // [D, H*DH]
    const float* out_b = (const float*)d_in[4];   // [D]

    float* qkv  = nullptr;
    float* attn = nullptr;
    cudaGetSymbolAddress((void**)&qkv,  g_qkv);
    cudaGetSymbolAddress((void**)&attn, g_attn);

    const int M = Bb * Nn;   // 4096

    // qkv = x @ W_w^T + W_b     [4096, 3072]
    sgemm_nt_bias<<<dim3(D3 / 128, M / 128), 256>>>(x, W_w, W_b, qkv, M, D3, Dd);

    // attention -> attn [B,N,H*DH]
    flash_attn_mma<<<dim3(Nn / 128, Hh, Bb), 256>>>(qkv, attn);

    // out = attn @ out_w^T + out_b   [4096, 1024]
    sgemm_nt_bias<<<dim3(Dd / 128, M / 128), 256>>>(attn, out_w, out_b,
                                                    (float*)d_out, M, Dd, Dd);
}

// round 3
// speedup vs baseline: 5.6875x; 1.4997x over previous
#include <cuda_runtime.h>
#include <math.h>
#include <stdint.h>

// Problem constants
constexpr int Bb  = 2;
constexpr int Nn  = 2048;
constexpr int Dd  = 1024;
constexpr int Hh  = 16;
constexpr int DHh = 64;
constexpr int D3  = 3 * Dd;   // 3072

// Scratch (allocation-free rule: __device__ globals)
__device__ float g_qkv[Bb * Nn * D3];    // [B,N,3*H*DH]
__device__ float g_attn[Bb * Nn * Dd];   // [B,N,H*DH]

// ---------------------------------------------------------------------------
// helpers
// ---------------------------------------------------------------------------
__device__ __forceinline__ uint32_t f2tf32(float x) {
    uint32_t r;
    asm("cvt.rna.tf32.f32 %0, %1;" : "=r"(r) : "f"(x));
    return r;
}
__device__ __forceinline__ float f2tf32f(float x) {
    return __uint_as_float(f2tf32(x));
}

__device__ __forceinline__ void mma_tf32(
    float& c0, float& c1, float& c2, float& c3,
    uint32_t a0, uint32_t a1, uint32_t a2, uint32_t a3,
    uint32_t b0, uint32_t b1)
{
    asm volatile(
        "mma.sync.aligned.m16n8k8.row.col.f32.tf32.tf32.f32 "
        "{%0,%1,%2,%3}, {%4,%5,%6,%7}, {%8,%9}, {%0,%1,%2,%3};\n"
        : "+f"(c0), "+f"(c1), "+f"(c2), "+f"(c3)
        : "r"(a0), "r"(a1), "r"(a2), "r"(a3), "r"(b0), "r"(b1));
}

// ---------------------------------------------------------------------------
// Tensor-core GEMM: C[M,N] = A[M,K] @ B[N,K]^T + bias[N]   (tf32 mma, fp32 acc)
// Block tile 128x64x32, 256 threads (8 warps). Warp w owns rows w*16..w*16+15
// across all 64 cols. A,B staged in smem row-major with pad-36 (all fragment
// LDS reads conflict-free). fp32->tf32 cvt.rna at staging time.
// Requires M%128==0, N%64==0, K%32==0.
// ---------------------------------------------------------------------------
__global__ __launch_bounds__(256) void tgemm_nt_bias(
    const float* __restrict__ A, const float* __restrict__ B,
    const float* __restrict__ bias, float* __restrict__ C,
    int M, int N, int K)
{
    __shared__ float As[128][36];
    __shared__ float Bs[64][36];

    const int tid  = threadIdx.x;
    const int lane = tid & 31;
    const int w    = tid >> 5;
    const int qr   = lane >> 2;     // group id
    const int qc   = lane & 3;      // thread-in-group
    const int m0   = blockIdx.y * 128;
    const int n0   = blockIdx.x * 64;
    const int row0 = w * 16;

    // global->smem loader mapping
    const int arow = tid >> 1;             // 0..127
    const int aseg = (tid & 1) * 16;       // 0 / 16
    const int brow = tid >> 2;             // 0..63
    const int bseg = (tid & 3) * 8;        // 0/8/16/24

    const float* Ag = A + (size_t)(m0 + arow) * K + aseg;
    const float* Bg = B + (size_t)(n0 + brow) * K + bseg;

    float acc[8][4];
    #pragma unroll
    for (int nt = 0; nt < 8; nt++)
        #pragma unroll
        for (int i = 0; i < 4; i++) acc[nt][i] = 0.f;

    // prefetch first chunk
    float4 ra0 = *(const float4*)(Ag + 0);
    float4 ra1 = *(const float4*)(Ag + 4);
    float4 ra2 = *(const float4*)(Ag + 8);
    float4 ra3 = *(const float4*)(Ag + 12);
    float4 rb0 = *(const float4*)(Bg + 0);
    float4 rb1 = *(const float4*)(Bg + 4);

    const int ktiles = K / 32;
    for (int kt = 0;;) {
        // stage (with tf32 rounding) into smem
        {
            float* ad = &As[arow][aseg];
            *(float4*)(ad + 0)  = make_float4(f2tf32f(ra0.x), f2tf32f(ra0.y), f2tf32f(ra0.z), f2tf32f(ra0.w));
            *(float4*)(ad + 4)  = make_float4(f2tf32f(ra1.x), f2tf32f(ra1.y), f2tf32f(ra1.z), f2tf32f(ra1.w));
            *(float4*)(ad + 8)  = make_float4(f2tf32f(ra2.x), f2tf32f(ra2.y), f2tf32f(ra2.z), f2tf32f(ra2.w));
            *(float4*)(ad + 12) = make_float4(f2tf32f(ra3.x), f2tf32f(ra3.y), f2tf32f(ra3.z), f2tf32f(ra3.w));
            float* bd = &Bs[brow][bseg];
            *(float4*)(bd + 0)  = make_float4(f2tf32f(rb0.x), f2tf32f(rb0.y), f2tf32f(rb0.z), f2tf32f(rb0.w));
            *(float4*)(bd + 4)  = make_float4(f2tf32f(rb1.x), f2tf32f(rb1.y), f2tf32f(rb1.z), f2tf32f(rb1.w));
        }
        __syncthreads();

        ++kt;
        if (kt < ktiles) {               // prefetch next chunk during compute
            Ag += 32; Bg += 32;
            ra0 = *(const float4*)(Ag + 0);
            ra1 = *(const float4*)(Ag + 4);
            ra2 = *(const float4*)(Ag + 8);
            ra3 = *(const float4*)(Ag + 12);
            rb0 = *(const float4*)(Bg + 0);
            rb1 = *(const float4*)(Bg + 4);
        }

        #pragma unroll
        for (int ks = 0; ks < 4; ks++) {
            const int kc = ks * 8 + qc;
            uint32_t a0 = __float_as_uint(As[row0 + qr][kc]);
            uint32_t a1 = __float_as_uint(As[row0 + qr + 8][kc]);
            uint32_t a2 = __float_as_uint(As[row0 + qr][kc + 4]);
            uint32_t a3 = __float_as_uint(As[row0 + qr + 8][kc + 4]);
            #pragma unroll
            for (int nt = 0; nt < 8; nt++) {
                uint32_t b0 = __float_as_uint(Bs[nt * 8 + qr][kc]);
                uint32_t b1 = __float_as_uint(Bs[nt * 8 + qr][kc + 4]);
                mma_tf32(acc[nt][0], acc[nt][1], acc[nt][2], acc[nt][3],
                         a0, a1, a2, a3, b0, b1);
            }
        }

        if (kt >= ktiles) break;
        __syncthreads();
    }

    // epilogue: bias + store (C fragment rows qr / qr+8, cols nt*8 + qc*2)
    float* Crow0 = C + (size_t)(m0 + row0 + qr) * N + n0;
    float* Crow1 = C + (size_t)(m0 + row0 + qr + 8) * N + n0;
    #pragma unroll
    for (int nt = 0; nt < 8; nt++) {
        const int c = nt * 8 + qc * 2;
        float2 bv = *(const float2*)&bias[n0 + c];
        *(float2*)&Crow0[c] = make_float2(acc[nt][0] + bv.x, acc[nt][1] + bv.y);
        *(float2*)&Crow1[c] = make_float2(acc[nt][2] + bv.x, acc[nt][3] + bv.y);
    }
}

// ---------------------------------------------------------------------------
// Flash attention on tensor cores (tf32 mma.sync), online softmax.
// (unchanged from R2)
// ---------------------------------------------------------------------------
__global__ __launch_bounds__(256, 1) void flash_attn_mma(
    const float* __restrict__ qkv, float* __restrict__ out)
{
    constexpr int KS = 68;
    constexpr int VS = 72;
    __shared__ float Ks[64 * KS];
    __shared__ float Vs[64 * VS];

    const int tid  = threadIdx.x;
    const int lane = tid & 31;
    const int w    = tid >> 5;
    const int qr   = lane >> 2;
    const int qc   = lane & 3;
    const int h    = blockIdx.y;
    const int b    = blockIdx.z;
    const int q0   = blockIdx.x * 128;
    const int row0 = w * 16;

    uint32_t Qa[8][4];
    {
        const float* qb    = qkv + ((size_t)(b * Nn + q0)) * D3 + h * DHh;
        const float* qrow0 = qb + (size_t)(row0 + qr) * D3;
        const float* qrow1 = qb + (size_t)(row0 + qr + 8) * D3;
        #pragma unroll
        for (int k = 0; k < 8; k++) {
            Qa[k][0] = f2tf32(qrow0[k * 8 + qc]     * 0.125f);
            Qa[k][1] = f2tf32(qrow1[k * 8 + qc]     * 0.125f);
            Qa[k][2] = f2tf32(qrow0[k * 8 + qc + 4] * 0.125f);
            Qa[k][3] = f2tf32(qrow1[k * 8 + qc + 4] * 0.125f);
        }
    }

    float O[8][4];
    #pragma unroll
    for (int nt = 0; nt < 8; nt++)
        #pragma unroll
        for (int i = 0; i < 4; i++) O[nt][i] = 0.f;
    float mA = -1e30f, mB = -1e30f, lA = 0.f, lB = 0.f;

    const int lrow = tid >> 2;
    const int lseg = (tid & 3) * 16;

    for (int t = 0; t < Nn / 64; t++) {
        const float* kb = qkv + ((size_t)(b * Nn + t * 64 + lrow)) * D3
                        + Dd + h * DHh + lseg;
        const float* vb = kb + Dd;
        __syncthreads();
        #pragma unroll
        for (int i = 0; i < 16; i += 4) {
            float4 kv = *(const float4*)(kb + i);
            float4 vv = *(const float4*)(vb + i);
            float* kd = &Ks[lrow * KS + lseg + i];
            float* vd = &Vs[lrow * VS + lseg + i];
            kd[0] = f2tf32f(kv.x); kd[1] = f2tf32f(kv.y);
            kd[2] = f2tf32f(kv.z); kd[3] = f2tf32f(kv.w);
            vd[0] = f2tf32f(vv.x); vd[1] = f2tf32f(vv.y);
            vd[2] = f2tf32f(vv.z); vd[3] = f2tf32f(vv.w);
        }
        __syncthreads();

        float S[8][4];
        #pragma unroll
        for (int nt = 0; nt < 8; nt++) {
            float c0 = 0.f, c1 = 0.f, c2 = 0.f, c3 = 0.f;
            const float* kbase = &Ks[(nt * 8 + qr) * KS + qc];
            #pragma unroll
            for (int k = 0; k < 8; k++) {
                uint32_t b0 = __float_as_uint(kbase[k * 8]);
                uint32_t b1 = __float_as_uint(kbase[k * 8 + 4]);
                mma_tf32(c0, c1, c2, c3,
                         Qa[k][0], Qa[k][1], Qa[k][2], Qa[k][3], b0, b1);
            }
            S[nt][0] = c0; S[nt][1] = c1; S[nt][2] = c2; S[nt][3] = c3;
        }

        float cmA = -1e30f, cmB = -1e30f;
        #pragma unroll
        for (int nt = 0; nt < 8; nt++) {
            cmA = fmaxf(cmA, fmaxf(S[nt][0], S[nt][1]));
            cmB = fmaxf(cmB, fmaxf(S[nt][2], S[nt][3]));
        }
        cmA = fmaxf(cmA, __shfl_xor_sync(0xffffffffu, cmA, 1));
        cmA = fmaxf(cmA, __shfl_xor_sync(0xffffffffu, cmA, 2));
        cmB = fmaxf(cmB, __shfl_xor_sync(0xffffffffu, cmB, 1));
        cmB = fmaxf(cmB, __shfl_xor_sync(0xffffffffu, cmB, 2));

        const float mnA = fmaxf(mA, cmA), mnB = fmaxf(mB, cmB);
        const float corrA = __expf(mA - mnA), corrB = __expf(mB - mnB);
        #pragma unroll
        for (int nt = 0; nt < 8; nt++) {
            O[nt][0] *= corrA; O[nt][1] *= corrA;
            O[nt][2] *= corrB; O[nt][3] *= corrB;
        }

        float psA = 0.f, psB = 0.f;
        const int quadbase = lane & ~3;
        const int s0l = quadbase | (qc >> 1);
        const int s1l = s0l + 2;
        const bool odd = qc & 1;
        #pragma unroll
        for (int ks = 0; ks < 8; ks++) {
            float p0 = __expf(S[ks][0] - mnA);
            float p1 = __expf(S[ks][1] - mnA);
            float p2 = __expf(S[ks][2] - mnB);
            float p3 = __expf(S[ks][3] - mnB);
            psA += p0 + p1;
            psB += p2 + p3;

            float g00 = __shfl_sync(0xffffffffu, p0, s0l);
            float g01 = __shfl_sync(0xffffffffu, p1, s0l);
            float g20 = __shfl_sync(0xffffffffu, p2, s0l);
            float g21 = __shfl_sync(0xffffffffu, p3, s0l);
            float h00 = __shfl_sync(0xffffffffu, p0, s1l);
            float h01 = __shfl_sync(0xffffffffu, p1, s1l);
            float h20 = __shfl_sync(0xffffffffu, p2, s1l);
            float h21 = __shfl_sync(0xffffffffu, p3, s1l);

            uint32_t a0 = f2tf32(odd ? g01 : g00);
            uint32_t a1 = f2tf32(odd ? g21 : g20);
            uint32_t a2 = f2tf32(odd ? h01 : h00);
            uint32_t a3 = f2tf32(odd ? h21 : h20);

            const float* vbase = &Vs[(ks * 8 + qc) * VS + qr];
            #pragma unroll
            for (int nt = 0; nt < 8; nt++) {
                uint32_t b0 = __float_as_uint(vbase[nt * 8]);
                uint32_t b1 = __float_as_uint(vbase[nt * 8 + 4 * VS]);
                mma_tf32(O[nt][0], O[nt][1], O[nt][2], O[nt][3],
                         a0, a1, a2, a3, b0, b1);
            }
        }
        psA += __shfl_xor_sync(0xffffffffu, psA, 1);
        psA += __shfl_xor_sync(0xffffffffu, psA, 2);
        psB += __shfl_xor_sync(0xffffffffu, psB, 1);
        psB += __shfl_xor_sync(0xffffffffu, psB, 2);
        lA = lA * corrA + psA; mA = mnA;
        lB = lB * corrB + psB; mB = mnB;
    }

    const float invA = 1.f / lA, invB = 1.f / lB;
    float* ob    = out + ((size_t)(b * Nn + q0)) * Dd + h * DHh;
    float* orow0 = ob + (size_t)(row0 + qr) * Dd;
    float* orow1 = ob + (size_t)(row0 + qr + 8) * Dd;
    #pragma unroll
    for (int nt = 0; nt < 8; nt++) {
        int c = nt * 8 + qc * 2;
        *(float2*)&orow0[c] = make_float2(O[nt][0] * invA, O[nt][1] * invA);
        *(float2*)&orow1[c] = make_float2(O[nt][2] * invB, O[nt][3] * invB);
    }
}

// ---------------------------------------------------------------------------
// Host launcher
// ---------------------------------------------------------------------------
extern "C" void kernel_launch(void* const* d_in, const int* in_sizes, int n_in,
                              void* d_out, int out_size)
{
    const float* x     = (const float*)d_in[0];   // [B,N,D]
    const float* W_w   = (const float*)d_in[1];   // [3*H*DH, D]
    const float* W_b   = (const float*)d_in[2];   // [3*H*DH]
    const float* out_w = (const float*)d_in[3];   // [D, H*DH]
    const float* out_b = (const float*)d_in[4];   // [D]

    float* qkv  = nullptr;
    float* attn = nullptr;
    cudaGetSymbolAddress((void**)&qkv,  g_qkv);
    cudaGetSymbolAddress((void**)&attn, g_attn);

    const int M = Bb * Nn;   // 4096

    // qkv = x @ W_w^T + W_b     [4096, 3072]
    tgemm_nt_bias<<<dim3(D3 / 64, M / 128), 256>>>(x, W_w, W_b, qkv, M, D3, Dd);

    // attention -> attn [B,N,H*DH]
    flash_attn_mma<<<dim3(Nn / 128, Hh, Bb), 256>>>(qkv, attn);

    // out = attn @ out_w^T + out_b   [4096, 1024]
    tgemm_nt_bias<<<dim3(Dd / 64, M / 128), 256>>>(attn, out_w, out_b,
                                                   (float*)d_out, M, Dd, Dd);
}

// round 4
// speedup vs baseline: 6.0746x; 1.0681x over previous
#include <cuda_runtime.h>
#include <math.h>
#include <stdint.h>

// Problem constants
constexpr int Bb  = 2;
constexpr int Nn  = 2048;
constexpr int Dd  = 1024;
constexpr int Hh  = 16;
constexpr int DHh = 64;
constexpr int D3  = 3 * Dd;   // 3072

// Scratch (allocation-free rule: __device__ globals)
__device__ float g_qkv[Bb * Nn * D3];    // [B,N,3*H*DH]
__device__ float g_attn[Bb * Nn * Dd];   // [B,N,H*DH]

// ---------------------------------------------------------------------------
// helpers
// ---------------------------------------------------------------------------
__device__ __forceinline__ uint32_t f2tf32(float x) {
    uint32_t r;
    asm("cvt.rna.tf32.f32 %0, %1;" : "=r"(r) : "f"(x));
    return r;
}
__device__ __forceinline__ float f2tf32f(float x) {
    return __uint_as_float(f2tf32(x));
}

__device__ __forceinline__ void mma_tf32(
    float& c0, float& c1, float& c2, float& c3,
    uint32_t a0, uint32_t a1, uint32_t a2, uint32_t a3,
    uint32_t b0, uint32_t b1)
{
    asm volatile(
        "mma.sync.aligned.m16n8k8.row.col.f32.tf32.tf32.f32 "
        "{%0,%1,%2,%3}, {%4,%5,%6,%7}, {%8,%9}, {%0,%1,%2,%3};\n"
        : "+f"(c0), "+f"(c1), "+f"(c2), "+f"(c3)
        : "r"(a0), "r"(a1), "r"(a2), "r"(a3), "r"(b0), "r"(b1));
}

// ---------------------------------------------------------------------------
// Tensor-core GEMM v2: C[M,N] = A[M,K] @ B[N,K]^T + bias[N]
// Block 128x128, K-chunk 16, double-buffered smem, 8 warps (4M x 2N),
// warp tile 32x64 (two m16 A-fragments share every B-fragment pair).
// Smem pad-20 rows: all fragment LDS conflict-free (banks qr*20 mod 32 + qc).
// One __syncthreads per chunk. Requires M%128==0, N%128==0, K%16==0.
// ---------------------------------------------------------------------------
__global__ __launch_bounds__(256) void tgemm_v2(
    const float* __restrict__ A, const float* __restrict__ B,
    const float* __restrict__ bias, float* __restrict__ C,
    int M, int N, int K)
{
    __shared__ float As[2][128][20];
    __shared__ float Bs[2][128][20];

    const int tid  = threadIdx.x;
    const int lane = tid & 31;
    const int w    = tid >> 5;
    const int qr   = lane >> 2;
    const int qc   = lane & 3;
    const int wm   = w & 3;         // M quadrant (32 rows)
    const int wn   = w >> 2;        // N half (64 cols)
    const int m0   = blockIdx.y * 128;
    const int n0   = blockIdx.x * 128;

    // global->smem loader mapping: 2 threads per row, 8 floats each
    const int arow = tid >> 1;
    const int aseg = (tid & 1) * 8;

    const float* Ag = A + (size_t)(m0 + arow) * K + aseg;
    const float* Bg = B + (size_t)(n0 + arow) * K + aseg;

    float acc[2][8][4];
    #pragma unroll
    for (int f = 0; f < 2; f++)
        #pragma unroll
        for (int nt = 0; nt < 8; nt++)
            #pragma unroll
            for (int i = 0; i < 4; i++) acc[f][nt][i] = 0.f;

    // prefetch chunk 0
    float4 ra0 = *(const float4*)(Ag + 0);
    float4 ra1 = *(const float4*)(Ag + 4);
    float4 rb0 = *(const float4*)(Bg + 0);
    float4 rb1 = *(const float4*)(Bg + 4);

    const int nch = K / 16;
    for (int ch = 0;;) {
        const int buf = ch & 1;
        {
            float* ad = &As[buf][arow][aseg];
            *(float4*)(ad + 0) = make_float4(f2tf32f(ra0.x), f2tf32f(ra0.y),
                                             f2tf32f(ra0.z), f2tf32f(ra0.w));
            *(float4*)(ad + 4) = make_float4(f2tf32f(ra1.x), f2tf32f(ra1.y),
                                             f2tf32f(ra1.z), f2tf32f(ra1.w));
            float* bd = &Bs[buf][arow][aseg];
            *(float4*)(bd + 0) = make_float4(f2tf32f(rb0.x), f2tf32f(rb0.y),
                                             f2tf32f(rb0.z), f2tf32f(rb0.w));
            *(float4*)(bd + 4) = make_float4(f2tf32f(rb1.x), f2tf32f(rb1.y),
                                             f2tf32f(rb1.z), f2tf32f(rb1.w));
        }
        __syncthreads();

        ++ch;
        if (ch < nch) {                 // prefetch next chunk during compute
            Ag += 16; Bg += 16;
            ra0 = *(const float4*)(Ag + 0);
            ra1 = *(const float4*)(Ag + 4);
            rb0 = *(const float4*)(Bg + 0);
            rb1 = *(const float4*)(Bg + 4);
        }

        #pragma unroll
        for (int ks = 0; ks < 2; ks++) {
            const int kc = ks * 8 + qc;
            uint32_t a[2][4];
            #pragma unroll
            for (int f = 0; f < 2; f++) {
                const int rbase = wm * 32 + f * 16;
                a[f][0] = __float_as_uint(As[buf][rbase + qr][kc]);
                a[f][1] = __float_as_uint(As[buf][rbase + qr + 8][kc]);
                a[f][2] = __float_as_uint(As[buf][rbase + qr][kc + 4]);
                a[f][3] = __float_as_uint(As[buf][rbase + qr + 8][kc + 4]);
            }
            #pragma unroll
            for (int nt = 0; nt < 8; nt++) {
                const int brow = wn * 64 + nt * 8 + qr;
                uint32_t b0 = __float_as_uint(Bs[buf][brow][kc]);
                uint32_t b1 = __float_as_uint(Bs[buf][brow][kc + 4]);
                mma_tf32(acc[0][nt][0], acc[0][nt][1], acc[0][nt][2], acc[0][nt][3],
                         a[0][0], a[0][1], a[0][2], a[0][3], b0, b1);
                mma_tf32(acc[1][nt][0], acc[1][nt][1], acc[1][nt][2], acc[1][nt][3],
                         a[1][0], a[1][1], a[1][2], a[1][3], b0, b1);
            }
        }

        if (ch >= nch) break;
        // no second sync: buffer written at ch+1 differs from buffer read here
    }

    // epilogue: bias + store
    #pragma unroll
    for (int f = 0; f < 2; f++) {
        const int r0 = m0 + wm * 32 + f * 16 + qr;
        float* Crow0 = C + (size_t)r0 * N + n0 + wn * 64;
        float* Crow1 = C + (size_t)(r0 + 8) * N + n0 + wn * 64;
        #pragma unroll
        for (int nt = 0; nt < 8; nt++) {
            const int c = nt * 8 + qc * 2;
            float2 bv = *(const float2*)&bias[n0 + wn * 64 + c];
            *(float2*)&Crow0[c] = make_float2(acc[f][nt][0] + bv.x,
                                              acc[f][nt][1] + bv.y);
            *(float2*)&Crow1[c] = make_float2(acc[f][nt][2] + bv.x,
                                              acc[f][nt][3] + bv.y);
        }
    }
}

// ---------------------------------------------------------------------------
// Flash attention on tensor cores (tf32 mma.sync), online softmax.
// (unchanged from R3)
// ---------------------------------------------------------------------------
__global__ __launch_bounds__(256, 1) void flash_attn_mma(
    const float* __restrict__ qkv, float* __restrict__ out)
{
    constexpr int KS = 68;
    constexpr int VS = 72;
    __shared__ float Ks[64 * KS];
    __shared__ float Vs[64 * VS];

    const int tid  = threadIdx.x;
    const int lane = tid & 31;
    const int w    = tid >> 5;
    const int qr   = lane >> 2;
    const int qc   = lane & 3;
    const int h    = blockIdx.y;
    const int b    = blockIdx.z;
    const int q0   = blockIdx.x * 128;
    const int row0 = w * 16;

    uint32_t Qa[8][4];
    {
        const float* qb    = qkv + ((size_t)(b * Nn + q0)) * D3 + h * DHh;
        const float* qrow0 = qb + (size_t)(row0 + qr) * D3;
        const float* qrow1 = qb + (size_t)(row0 + qr + 8) * D3;
        #pragma unroll
        for (int k = 0; k < 8; k++) {
            Qa[k][0] = f2tf32(qrow0[k * 8 + qc]     * 0.125f);
            Qa[k][1] = f2tf32(qrow1[k * 8 + qc]     * 0.125f);
            Qa[k][2] = f2tf32(qrow0[k * 8 + qc + 4] * 0.125f);
            Qa[k][3] = f2tf32(qrow1[k * 8 + qc + 4] * 0.125f);
        }
    }

    float O[8][4];
    #pragma unroll
    for (int nt = 0; nt < 8; nt++)
        #pragma unroll
        for (int i = 0; i < 4; i++) O[nt][i] = 0.f;
    float mA = -1e30f, mB = -1e30f, lA = 0.f, lB = 0.f;

    const int lrow = tid >> 2;
    const int lseg = (tid & 3) * 16;

    for (int t = 0; t < Nn / 64; t++) {
        const float* kb = qkv + ((size_t)(b * Nn + t * 64 + lrow)) * D3
                        + Dd + h * DHh + lseg;
        const float* vb = kb + Dd;
        __syncthreads();
        #pragma unroll
        for (int i = 0; i < 16; i += 4) {
            float4 kv = *(const float4*)(kb + i);
            float4 vv = *(const float4*)(vb + i);
            float* kd = &Ks[lrow * KS + lseg + i];
            float* vd = &Vs[lrow * VS + lseg + i];
            kd[0] = f2tf32f(kv.x); kd[1] = f2tf32f(kv.y);
            kd[2] = f2tf32f(kv.z); kd[3] = f2tf32f(kv.w);
            vd[0] = f2tf32f(vv.x); vd[1] = f2tf32f(vv.y);
            vd[2] = f2tf32f(vv.z); vd[3] = f2tf32f(vv.w);
        }
        __syncthreads();

        float S[8][4];
        #pragma unroll
        for (int nt = 0; nt < 8; nt++) {
            float c0 = 0.f, c1 = 0.f, c2 = 0.f, c3 = 0.f;
            const float* kbase = &Ks[(nt * 8 + qr) * KS + qc];
            #pragma unroll
            for (int k = 0; k < 8; k++) {
                uint32_t b0 = __float_as_uint(kbase[k * 8]);
                uint32_t b1 = __float_as_uint(kbase[k * 8 + 4]);
                mma_tf32(c0, c1, c2, c3,
                         Qa[k][0], Qa[k][1], Qa[k][2], Qa[k][3], b0, b1);
            }
            S[nt][0] = c0; S[nt][1] = c1; S[nt][2] = c2; S[nt][3] = c3;
        }

        float cmA = -1e30f, cmB = -1e30f;
        #pragma unroll
        for (int nt = 0; nt < 8; nt++) {
            cmA = fmaxf(cmA, fmaxf(S[nt][0], S[nt][1]));
            cmB = fmaxf(cmB, fmaxf(S[nt][2], S[nt][3]));
        }
        cmA = fmaxf(cmA, __shfl_xor_sync(0xffffffffu, cmA, 1));
        cmA = fmaxf(cmA, __shfl_xor_sync(0xffffffffu, cmA, 2));
        cmB = fmaxf(cmB, __shfl_xor_sync(0xffffffffu, cmB, 1));
        cmB = fmaxf(cmB, __shfl_xor_sync(0xffffffffu, cmB, 2));

        const float mnA = fmaxf(mA, cmA), mnB = fmaxf(mB, cmB);
        const float corrA = __expf(mA - mnA), corrB = __expf(mB - mnB);
        #pragma unroll
        for (int nt = 0; nt < 8; nt++) {
            O[nt][0] *= corrA; O[nt][1] *= corrA;
            O[nt][2] *= corrB; O[nt][3] *= corrB;
        }

        float psA = 0.f, psB = 0.f;
        const int quadbase = lane & ~3;
        const int s0l = quadbase | (qc >> 1);
        const int s1l = s0l + 2;
        const bool odd = qc & 1;
        #pragma unroll
        for (int ks = 0; ks < 8; ks++) {
            float p0 = __expf(S[ks][0] - mnA);
            float p1 = __expf(S[ks][1] - mnA);
            float p2 = __expf(S[ks][2] - mnB);
            float p3 = __expf(S[ks][3] - mnB);
            psA += p0 + p1;
            psB += p2 + p3;

            float g00 = __shfl_sync(0xffffffffu, p0, s0l);
            float g01 = __shfl_sync(0xffffffffu, p1, s0l);
            float g20 = __shfl_sync(0xffffffffu, p2, s0l);
            float g21 = __shfl_sync(0xffffffffu, p3, s0l);
            float h00 = __shfl_sync(0xffffffffu, p0, s1l);
            float h01 = __shfl_sync(0xffffffffu, p1, s1l);
            float h20 = __shfl_sync(0xffffffffu, p2, s1l);
            float h21 = __shfl_sync(0xffffffffu, p3, s1l);

            uint32_t a0 = f2tf32(odd ? g01 : g00);
            uint32_t a1 = f2tf32(odd ? g21 : g20);
            uint32_t a2 = f2tf32(odd ? h01 : h00);
            uint32_t a3 = f2tf32(odd ? h21 : h20);

            const float* vbase = &Vs[(ks * 8 + qc) * VS + qr];
            #pragma unroll
            for (int nt = 0; nt < 8; nt++) {
                uint32_t b0 = __float_as_uint(vbase[nt * 8]);
                uint32_t b1 = __float_as_uint(vbase[nt * 8 + 4 * VS]);
                mma_tf32(O[nt][0], O[nt][1], O[nt][2], O[nt][3],
                         a0, a1, a2, a3, b0, b1);
            }
        }
        psA += __shfl_xor_sync(0xffffffffu, psA, 1);
        psA += __shfl_xor_sync(0xffffffffu, psA, 2);
        psB += __shfl_xor_sync(0xffffffffu, psB, 1);
        psB += __shfl_xor_sync(0xffffffffu, psB, 2);
        lA = lA * corrA + psA; mA = mnA;
        lB = lB * corrB + psB; mB = mnB;
    }

    const float invA = 1.f / lA, invB = 1.f / lB;
    float* ob    = out + ((size_t)(b * Nn + q0)) * Dd + h * DHh;
    float* orow0 = ob + (size_t)(row0 + qr) * Dd;
    float* orow1 = ob + (size_t)(row0 + qr + 8) * Dd;
    #pragma unroll
    for (int nt = 0; nt < 8; nt++) {
        int c = nt * 8 + qc * 2;
        *(float2*)&orow0[c] = make_float2(O[nt][0] * invA, O[nt][1] * invA);
        *(float2*)&orow1[c] = make_float2(O[nt][2] * invB, O[nt][3] * invB);
    }
}

// ---------------------------------------------------------------------------
// Host launcher
// ---------------------------------------------------------------------------
extern "C" void kernel_launch(void* const* d_in, const int* in_sizes, int n_in,
                              void* d_out, int out_size)
{
    const float* x     = (const float*)d_in[0];   // [B,N,D]
    const float* W_w   = (const float*)d_in[1];   // [3*H*DH, D]
    const float* W_b   = (const float*)d_in[2];   // [3*H*DH]
    const float* out_w = (const float*)d_in[3];   // [D, H*DH]
    const float* out_b = (const float*)d_in[4];   // [D]

    float* qkv  = nullptr;
    float* attn = nullptr;
    cudaGetSymbolAddress((void**)&qkv,  g_qkv);
    cudaGetSymbolAddress((void**)&attn, g_attn);

    const int M = Bb * Nn;   // 4096

    // qkv = x @ W_w^T + W_b     [4096, 3072]
    tgemm_v2<<<dim3(D3 / 128, M / 128), 256>>>(x, W_w, W_b, qkv, M, D3, Dd);

    // attention -> attn [B,N,H*DH]
    flash_attn_mma<<<dim3(Nn / 128, Hh, Bb), 256>>>(qkv, attn);

    // out = attn @ out_w^T + out_b   [4096, 1024]
    tgemm_v2<<<dim3(Dd / 128, M / 128), 256>>>(attn, out_w, out_b,
                                               (float*)d_out, M, Dd, Dd);
}

// round 5
// speedup vs baseline: 6.5242x; 1.0740x over previous
#include <cuda_runtime.h>
#include <math.h>
#include <stdint.h>

// Problem constants
constexpr int Bb  = 2;
constexpr int Nn  = 2048;
constexpr int Dd  = 1024;
constexpr int Hh  = 16;
constexpr int DHh = 64;
constexpr int D3  = 3 * Dd;   // 3072

// Scratch (allocation-free rule: __device__ globals)
__device__ float g_qkv[Bb * Nn * D3];    // [B,N,3*H*DH]
__device__ float g_attn[Bb * Nn * Dd];   // [B,N,H*DH]

// ---------------------------------------------------------------------------
// helpers
// ---------------------------------------------------------------------------
__device__ __forceinline__ uint32_t f2tf32(float x) {
    uint32_t r;
    asm("cvt.rna.tf32.f32 %0, %1;" : "=r"(r) : "f"(x));
    return r;
}
__device__ __forceinline__ float f2tf32f(float x) {
    return __uint_as_float(f2tf32(x));
}

__device__ __forceinline__ void mma_tf32(
    float& c0, float& c1, float& c2, float& c3,
    uint32_t a0, uint32_t a1, uint32_t a2, uint32_t a3,
    uint32_t b0, uint32_t b1)
{
    asm volatile(
        "mma.sync.aligned.m16n8k8.row.col.f32.tf32.tf32.f32 "
        "{%0,%1,%2,%3}, {%4,%5,%6,%7}, {%8,%9}, {%0,%1,%2,%3};\n"
        : "+f"(c0), "+f"(c1), "+f"(c2), "+f"(c3)
        : "r"(a0), "r"(a1), "r"(a2), "r"(a3), "r"(b0), "r"(b1));
}

// ---------------------------------------------------------------------------
// Tensor-core GEMM v3: C[M,N] = A[M,K] @ B[N,K]^T + bias[N]
// Block 128x128, K-chunk 16, double-buffered smem, 8 warps (4M x 2N),
// warp tile 32x64.
// Smem layout: row stride 16 (no pad). Within a row, the K-chunk element d
// is stored at column  s0(d) ^ g(row),
//   s0(d) = 8*(d>>3) + 2*(d&3) + ((d>>2)&1)   (puts mma pairs (d,d+4) adjacent)
//   g(r)  = 8*((r>>1)&1) + 4*((r>>2)&1) + 2*((r>>3)&1)   (bank xor-swizzle)
// => every fragment load is one conflict-free LDS.64; staging stores are
// 2-way at worst. One __syncthreads per chunk.
// Requires M%128==0, N%128==0, K%16==0.
// ---------------------------------------------------------------------------
__global__ __launch_bounds__(256) void tgemm_v3(
    const float* __restrict__ A, const float* __restrict__ B,
    const float* __restrict__ bias, float* __restrict__ C,
    int M, int N, int K)
{
    __shared__ float As[2][128][16];
    __shared__ float Bs[2][128][16];

    const int tid  = threadIdx.x;
    const int lane = tid & 31;
    const int w    = tid >> 5;
    const int qr   = lane >> 2;
    const int qc   = lane & 3;
    const int wm   = w & 3;         // M quadrant (32 rows)
    const int wn   = w >> 2;        // N half (64 cols)
    const int m0   = blockIdx.y * 128;
    const int n0   = blockIdx.x * 128;

    // loader mapping: 2 threads per row, 8 consecutive k each
    const int arow = tid >> 1;
    const int h    = tid & 1;
    const int ga   = 8 * ((arow >> 1) & 1) + 4 * ((arow >> 2) & 1)
                   + 2 * ((arow >> 3) & 1);
    // staging float2 column indices (within 8-slot float2 row)
    const int sc0 = ((8 * h + 0) ^ ga) >> 1;
    const int sc1 = ((8 * h + 2) ^ ga) >> 1;
    const int sc2 = ((8 * h + 4) ^ ga) >> 1;
    const int sc3 = ((8 * h + 6) ^ ga) >> 1;

    // fragment column base (bits 1-3), xor'd with 8*ks and 2*(row bit3)
    const int cb = (2 * qc) ^ (8 * ((qr >> 1) & 1) + 4 * ((qr >> 2) & 1));

    const float* Ag = A + (size_t)(m0 + arow) * K + h * 8;
    const float* Bg = B + (size_t)(n0 + arow) * K + h * 8;

    float acc[2][8][4];
    #pragma unroll
    for (int f = 0; f < 2; f++)
        #pragma unroll
        for (int nt = 0; nt < 8; nt++)
            #pragma unroll
            for (int i = 0; i < 4; i++) acc[f][nt][i] = 0.f;

    // prefetch chunk 0
    float4 ra0 = *(const float4*)(Ag + 0);
    float4 ra1 = *(const float4*)(Ag + 4);
    float4 rb0 = *(const float4*)(Bg + 0);
    float4 rb1 = *(const float4*)(Bg + 4);

    const int nch = K / 16;
    for (int ch = 0;;) {
        const int buf = ch & 1;
        {
            float2* ad = (float2*)&As[buf][arow][0];
            ad[sc0] = make_float2(f2tf32f(ra0.x), f2tf32f(ra1.x));
            ad[sc1] = make_float2(f2tf32f(ra0.y), f2tf32f(ra1.y));
            ad[sc2] = make_float2(f2tf32f(ra0.z), f2tf32f(ra1.z));
            ad[sc3] = make_float2(f2tf32f(ra0.w), f2tf32f(ra1.w));
            float2* bd = (float2*)&Bs[buf][arow][0];
            bd[sc0] = make_float2(f2tf32f(rb0.x), f2tf32f(rb1.x));
            bd[sc1] = make_float2(f2tf32f(rb0.y), f2tf32f(rb1.y));
            bd[sc2] = make_float2(f2tf32f(rb0.z), f2tf32f(rb1.z));
            bd[sc3] = make_float2(f2tf32f(rb0.w), f2tf32f(rb1.w));
        }
        __syncthreads();

        ++ch;
        if (ch < nch) {                 // prefetch next chunk during compute
            Ag += 16; Bg += 16;
            ra0 = *(const float4*)(Ag + 0);
            ra1 = *(const float4*)(Ag + 4);
            rb0 = *(const float4*)(Bg + 0);
            rb1 = *(const float4*)(Bg + 4);
        }

        #pragma unroll
        for (int ks = 0; ks < 2; ks++) {
            const int cks = cb ^ (8 * ks);
            uint32_t a[2][4];
            #pragma unroll
            for (int f = 0; f < 2; f++) {
                const float2* r0p =
                    (const float2*)&As[buf][wm * 32 + f * 16 + qr][0];
                const float2* r1p =
                    (const float2*)&As[buf][wm * 32 + f * 16 + 8 + qr][0];
                float2 va = r0p[cks >> 1];           // rows with bit3=0
                float2 vb = r1p[(cks ^ 2) >> 1];     // rows with bit3=1
                a[f][0] = __float_as_uint(va.x);
                a[f][1] = __float_as_uint(vb.x);
                a[f][2] = __float_as_uint(va.y);
                a[f][3] = __float_as_uint(vb.y);
            }
            #pragma unroll
            for (int nt = 0; nt < 8; nt++) {
                const float2* bp =
                    (const float2*)&Bs[buf][wn * 64 + nt * 8 + qr][0];
                float2 v = bp[(cks ^ (2 * (nt & 1))) >> 1];
                uint32_t b0 = __float_as_uint(v.x);
                uint32_t b1 = __float_as_uint(v.y);
                mma_tf32(acc[0][nt][0], acc[0][nt][1], acc[0][nt][2], acc[0][nt][3],
                         a[0][0], a[0][1], a[0][2], a[0][3], b0, b1);
                mma_tf32(acc[1][nt][0], acc[1][nt][1], acc[1][nt][2], acc[1][nt][3],
                         a[1][0], a[1][1], a[1][2], a[1][3], b0, b1);
            }
        }

        if (ch >= nch) break;
        // no second sync: next iteration writes the other buffer
    }

    // epilogue: bias + store
    #pragma unroll
    for (int f = 0; f < 2; f++) {
        const int r0 = m0 + wm * 32 + f * 16 + qr;
        float* Crow0 = C + (size_t)r0 * N + n0 + wn * 64;
        float* Crow1 = C + (size_t)(r0 + 8) * N + n0 + wn * 64;
        #pragma unroll
        for (int nt = 0; nt < 8; nt++) {
            const int c = nt * 8 + qc * 2;
            float2 bv = *(const float2*)&bias[n0 + wn * 64 + c];
            *(float2*)&Crow0[c] = make_float2(acc[f][nt][0] + bv.x,
                                              acc[f][nt][1] + bv.y);
            *(float2*)&Crow1[c] = make_float2(acc[f][nt][2] + bv.x,
                                              acc[f][nt][3] + bv.y);
        }
    }
}

// ---------------------------------------------------------------------------
// Flash attention on tensor cores (tf32 mma.sync), online softmax.
// R5 change: K/V tile for iteration t+1 is LDG'd right after the second
// barrier, so global latency is hidden under the compute phase, instead of
// being exposed between the two barriers.
// ---------------------------------------------------------------------------
__global__ __launch_bounds__(256, 1) void flash_attn_mma(
    const float* __restrict__ qkv, float* __restrict__ out)
{
    constexpr int KS = 68;
    constexpr int VS = 72;
    __shared__ float Ks[64 * KS];
    __shared__ float Vs[64 * VS];

    const int tid  = threadIdx.x;
    const int lane = tid & 31;
    const int w    = tid >> 5;
    const int qr   = lane >> 2;
    const int qc   = lane & 3;
    const int h    = blockIdx.y;
    const int b    = blockIdx.z;
    const int q0   = blockIdx.x * 128;
    const int row0 = w * 16;

    uint32_t Qa[8][4];
    {
        const float* qb    = qkv + ((size_t)(b * Nn + q0)) * D3 + h * DHh;
        const float* qrow0 = qb + (size_t)(row0 + qr) * D3;
        const float* qrow1 = qb + (size_t)(row0 + qr + 8) * D3;
        #pragma unroll
        for (int k = 0; k < 8; k++) {
            Qa[k][0] = f2tf32(qrow0[k * 8 + qc]     * 0.125f);
            Qa[k][1] = f2tf32(qrow1[k * 8 + qc]     * 0.125f);
            Qa[k][2] = f2tf32(qrow0[k * 8 + qc + 4] * 0.125f);
            Qa[k][3] = f2tf32(qrow1[k * 8 + qc + 4] * 0.125f);
        }
    }

    float O[8][4];
    #pragma unroll
    for (int nt = 0; nt < 8; nt++)
        #pragma unroll
        for (int i = 0; i < 4; i++) O[nt][i] = 0.f;
    float mA = -1e30f, mB = -1e30f, lA = 0.f, lB = 0.f;

    const int lrow = tid >> 2;
    const int lseg = (tid & 3) * 16;

    // prefetch tile 0 into registers
    float4 kr[4], vr[4];
    {
        const float* kb = qkv + ((size_t)(b * Nn + lrow)) * D3
                        + Dd + h * DHh + lseg;
        const float* vb = kb + Dd;
        #pragma unroll
        for (int i = 0; i < 4; i++) {
            kr[i] = *(const float4*)(kb + i * 4);
            vr[i] = *(const float4*)(vb + i * 4);
        }
    }

    for (int t = 0; t < Nn / 64; t++) {
        __syncthreads();   // previous tile fully consumed (no-op at t=0)
        {
            float* kd = &Ks[lrow * KS + lseg];
            float* vd = &Vs[lrow * VS + lseg];
            #pragma unroll
            for (int i = 0; i < 4; i++) {
                kd[i * 4 + 0] = f2tf32f(kr[i].x);
                kd[i * 4 + 1] = f2tf32f(kr[i].y);
                kd[i * 4 + 2] = f2tf32f(kr[i].z);
                kd[i * 4 + 3] = f2tf32f(kr[i].w);
                vd[i * 4 + 0] = f2tf32f(vr[i].x);
                vd[i * 4 + 1] = f2tf32f(vr[i].y);
                vd[i * 4 + 2] = f2tf32f(vr[i].z);
                vd[i * 4 + 3] = f2tf32f(vr[i].w);
            }
        }
        __syncthreads();

        if (t + 1 < Nn / 64) {   // LDG next tile; flies under compute below
            const float* kb = qkv + ((size_t)(b * Nn + (t + 1) * 64 + lrow)) * D3
                            + Dd + h * DHh + lseg;
            const float* vb = kb + Dd;
            #pragma unroll
            for (int i = 0; i < 4; i++) {
                kr[i] = *(const float4*)(kb + i * 4);
                vr[i] = *(const float4*)(vb + i * 4);
            }
        }

        float S[8][4];
        #pragma unroll
        for (int nt = 0; nt < 8; nt++) {
            float c0 = 0.f, c1 = 0.f, c2 = 0.f, c3 = 0.f;
            const float* kbase = &Ks[(nt * 8 + qr) * KS + qc];
            #pragma unroll
            for (int k = 0; k < 8; k++) {
                uint32_t b0 = __float_as_uint(kbase[k * 8]);
                uint32_t b1 = __float_as_uint(kbase[k * 8 + 4]);
                mma_tf32(c0, c1, c2, c3,
                         Qa[k][0], Qa[k][1], Qa[k][2], Qa[k][3], b0, b1);
            }
            S[nt][0] = c0; S[nt][1] = c1; S[nt][2] = c2; S[nt][3] = c3;
        }

        float cmA = -1e30f, cmB = -1e30f;
        #pragma unroll
        for (int nt = 0; nt < 8; nt++) {
            cmA = fmaxf(cmA, fmaxf(S[nt][0], S[nt][1]));
            cmB = fmaxf(cmB, fmaxf(S[nt][2], S[nt][3]));
        }
        cmA = fmaxf(cmA, __shfl_xor_sync(0xffffffffu, cmA, 1));
        cmA = fmaxf(cmA, __shfl_xor_sync(0xffffffffu, cmA, 2));
        cmB = fmaxf(cmB, __shfl_xor_sync(0xffffffffu, cmB, 1));
        cmB = fmaxf(cmB, __shfl_xor_sync(0xffffffffu, cmB, 2));

        const float mnA = fmaxf(mA, cmA), mnB = fmaxf(mB, cmB);
        const float corrA = __expf(mA - mnA), corrB = __expf(mB - mnB);
        #pragma unroll
        for (int nt = 0; nt < 8; nt++) {
            O[nt][0] *= corrA; O[nt][1] *= corrA;
            O[nt][2] *= corrB; O[nt][3] *= corrB;
        }

        float psA = 0.f, psB = 0.f;
        const int quadbase = lane & ~3;
        const int s0l = quadbase | (qc >> 1);
        const int s1l = s0l + 2;
        const bool odd = qc & 1;
        #pragma unroll
        for (int ks = 0; ks < 8; ks++) {
            float p0 = __expf(S[ks][0] - mnA);
            float p1 = __expf(S[ks][1] - mnA);
            float p2 = __expf(S[ks][2] - mnB);
            float p3 = __expf(S[ks][3] - mnB);
            psA += p0 + p1;
            psB += p2 + p3;

            float g00 = __shfl_sync(0xffffffffu, p0, s0l);
            float g01 = __shfl_sync(0xffffffffu, p1, s0l);
            float g20 = __shfl_sync(0xffffffffu, p2, s0l);
            float g21 = __shfl_sync(0xffffffffu, p3, s0l);
            float h00 = __shfl_sync(0xffffffffu, p0, s1l);
            float h01 = __shfl_sync(0xffffffffu, p1, s1l);
            float h20 = __shfl_sync(0xffffffffu, p2, s1l);
            float h21 = __shfl_sync(0xffffffffu, p3, s1l);

            uint32_t a0 = f2tf32(odd ? g01 : g00);
            uint32_t a1 = f2tf32(odd ? g21 : g20);
            uint32_t a2 = f2tf32(odd ? h01 : h00);
            uint32_t a3 = f2tf32(odd ? h21 : h20);

            const float* vbase = &Vs[(ks * 8 + qc) * VS + qr];
            #pragma unroll
            for (int nt = 0; nt < 8; nt++) {
                uint32_t b0 = __float_as_uint(vbase[nt * 8]);
                uint32_t b1 = __float_as_uint(vbase[nt * 8 + 4 * VS]);
                mma_tf32(O[nt][0], O[nt][1], O[nt][2], O[nt][3],
                         a0, a1, a2, a3, b0, b1);
            }
        }
        psA += __shfl_xor_sync(0xffffffffu, psA, 1);
        psA += __shfl_xor_sync(0xffffffffu, psA, 2);
        psB += __shfl_xor_sync(0xffffffffu, psB, 1);
        psB += __shfl_xor_sync(0xffffffffu, psB, 2);
        lA = lA * corrA + psA; mA = mnA;
        lB = lB * corrB + psB; mB = mnB;
    }

    const float invA = 1.f / lA, invB = 1.f / lB;
    float* ob    = out + ((size_t)(b * Nn + q0)) * Dd + h * DHh;
    float* orow0 = ob + (size_t)(row0 + qr) * Dd;
    float* orow1 = ob + (size_t)(row0 + qr + 8) * Dd;
    #pragma unroll
    for (int nt = 0; nt < 8; nt++) {
        int c = nt * 8 + qc * 2;
        *(float2*)&orow0[c] = make_float2(O[nt][0] * invA, O[nt][1] * invA);
        *(float2*)&orow1[c] = make_float2(O[nt][2] * invB, O[nt][3] * invB);
    }
}

// ---------------------------------------------------------------------------
// Host launcher
// ---------------------------------------------------------------------------
extern "C" void kernel_launch(void* const* d_in, const int* in_sizes, int n_in,
                              void* d_out, int out_size)
{
    const float* x     = (const float*)d_in[0];   // [B,N,D]
    const float* W_w   = (const float*)d_in[1];   // [3*H*DH, D]
    const float* W_b   = (const float*)d_in[2];   // [3*H*DH]
    const float* out_w = (const float*)d_in[3];   // [D, H*DH]
    const float* out_b = (const float*)d_in[4];   // [D]

    float* qkv  = nullptr;
    float* attn = nullptr;
    cudaGetSymbolAddress((void**)&qkv,  g_qkv);
    cudaGetSymbolAddress((void**)&attn, g_attn);

    const int M = Bb * Nn;   // 4096

    // qkv = x @ W_w^T + W_b     [4096, 3072]
    tgemm_v3<<<dim3(D3 / 128, M / 128), 256>>>(x, W_w, W_b, qkv, M, D3, Dd);

    // attention -> attn [B,N,H*DH]
    flash_attn_mma<<<dim3(Nn / 128, Hh, Bb), 256>>>(qkv, attn);

    // out = attn @ out_w^T + out_b   [4096, 1024]
    tgemm_v3<<<dim3(Dd / 128, M / 128), 256>>>(attn, out_w, out_b,
                                               (float*)d_out, M, Dd, Dd);
}

// round 6
// speedup vs baseline: 7.0879x; 1.0864x over previous
#include <cuda_runtime.h>
#include <math.h>
#include <stdint.h>

// Problem constants
constexpr int Bb  = 2;
constexpr int Nn  = 2048;
constexpr int Dd  = 1024;
constexpr int Hh  = 16;
constexpr int DHh = 64;
constexpr int D3  = 3 * Dd;   // 3072
constexpr int STAGES = 3;

// Scratch (allocation-free rule: __device__ globals)
__device__ float g_qkv[Bb * Nn * D3];     // [B,N,3*H*DH]
__device__ float g_attn[Bb * Nn * Dd];    // [B,N,H*DH]
__device__ float g_xr[Bb * Nn * Dd];      // x, tf32-rounded + repacked
__device__ float g_wwr[D3 * Dd];          // W_w, rounded + repacked
__device__ float g_owr[Dd * Dd];          // out_w, rounded + repacked
__device__ float g_attnr[Bb * Nn * Dd];   // attn, rounded + repacked

// ---------------------------------------------------------------------------
// helpers
// ---------------------------------------------------------------------------
__device__ __forceinline__ uint32_t f2tf32(float x) {
    uint32_t r;
    asm("cvt.rna.tf32.f32 %0, %1;" : "=r"(r) : "f"(x));
    return r;
}
__device__ __forceinline__ float f2tf32f(float x) {
    return __uint_as_float(f2tf32(x));
}

__device__ __forceinline__ void mma_tf32(
    float& c0, float& c1, float& c2, float& c3,
    uint32_t a0, uint32_t a1, uint32_t a2, uint32_t a3,
    uint32_t b0, uint32_t b1)
{
    asm volatile(
        "mma.sync.aligned.m16n8k8.row.col.f32.tf32.tf32.f32 "
        "{%0,%1,%2,%3}, {%4,%5,%6,%7}, {%8,%9}, {%0,%1,%2,%3};\n"
        : "+f"(c0), "+f"(c1), "+f"(c2), "+f"(c3)
        : "r"(a0), "r"(a1), "r"(a2), "r"(a3), "r"(b0), "r"(b1));
}

__device__ __forceinline__ void cp_async16(uint32_t smem, const void* g) {
    asm volatile("cp.async.cg.shared.global [%0], [%1], 16;\n"
                 :: "r"(smem), "l"(g));
}

// ---------------------------------------------------------------------------
// Round to tf32 (rna) + repack: within each 16-float group, out[4*(j%4)+j/4]
// = in[j]  (4x4 transpose). After this, floats {k, k+4, k+8, k+12} of a
// K-16 chunk are 16 contiguous bytes -> single LDS.128 per mma fragment.
// ---------------------------------------------------------------------------
__global__ void repack_tf32(const float* __restrict__ in,
                            float* __restrict__ out, int ngroups)
{
    int g = blockIdx.x * blockDim.x + threadIdx.x;
    if (g >= ngroups) return;
    const float4* ip = (const float4*)in + (size_t)g * 4;
    float4 v0 = ip[0], v1 = ip[1], v2 = ip[2], v3 = ip[3];
    float4* op = (float4*)out + (size_t)g * 4;
    op[0] = make_float4(f2tf32f(v0.x), f2tf32f(v1.x), f2tf32f(v2.x), f2tf32f(v3.x));
    op[1] = make_float4(f2tf32f(v0.y), f2tf32f(v1.y), f2tf32f(v2.y), f2tf32f(v3.y));
    op[2] = make_float4(f2tf32f(v0.z), f2tf32f(v1.z), f2tf32f(v2.z), f2tf32f(v3.z));
    op[3] = make_float4(f2tf32f(v0.w), f2tf32f(v1.w), f2tf32f(v2.w), f2tf32f(v3.w));
}

// ---------------------------------------------------------------------------
// Tensor-core GEMM v4: C[M,N] = A[M,K] @ B[N,K]^T + bias[N]
// A and B are PRE-ROUNDED (tf32) and PRE-REPACKED (4x4 within 16).
// Block 128x128, K-chunk 16, 3-stage cp.async pipeline, 8 warps (4M x 2N),
// warp tile 32x64. Fragment loads are single LDS.128 (conflict-free).
// Requires M%128==0, N%128==0, K%16==0.
// ---------------------------------------------------------------------------
__global__ __launch_bounds__(256, 2) void tgemm_v4(
    const float* __restrict__ A, const float* __restrict__ B,
    const float* __restrict__ bias, float* __restrict__ C,
    int M, int N, int K)
{
    __shared__ float4 As[STAGES][512];   // [stage][row*4 + g]  (8KB/stage)
    __shared__ float4 Bs[STAGES][512];

    const int tid  = threadIdx.x;
    const int lane = tid & 31;
    const int w    = tid >> 5;
    const int qr   = lane >> 2;
    const int qc   = lane & 3;
    const int wm   = w & 3;
    const int wn   = w >> 2;
    const int m0   = blockIdx.y * 128;
    const int n0   = blockIdx.x * 128;

    // loader mapping: thread t handles float4 slots t and t+256 of each tile
    const int r0 = tid >> 2;       // rows 0..63 (m=0) / 64..127 (m=1)
    const int g0 = tid & 3;
    const float* Ag0 = A + (size_t)(m0 + r0) * K + g0 * 4;
    const float* Ag1 = A + (size_t)(m0 + 64 + r0) * K + g0 * 4;
    const float* Bg0 = B + (size_t)(n0 + r0) * K + g0 * 4;
    const float* Bg1 = B + (size_t)(n0 + 64 + r0) * K + g0 * 4;

    uint32_t sA[STAGES], sB[STAGES];
    #pragma unroll
    for (int s = 0; s < STAGES; s++) {
        sA[s] = (uint32_t)__cvta_generic_to_shared(&As[s][tid]);
        sB[s] = (uint32_t)__cvta_generic_to_shared(&Bs[s][tid]);
    }

    float acc[2][8][4];
    #pragma unroll
    for (int f = 0; f < 2; f++)
        #pragma unroll
        for (int nt = 0; nt < 8; nt++)
            #pragma unroll
            for (int i = 0; i < 4; i++) acc[f][nt][i] = 0.f;

    const int nch = K / 16;

    // prefetch chunks 0..STAGES-2
    #pragma unroll
    for (int s = 0; s < STAGES - 1; s++) {
        cp_async16(sA[s],            Ag0 + s * 16);
        cp_async16(sA[s] + 256 * 16, Ag1 + s * 16);
        cp_async16(sB[s],            Bg0 + s * 16);
        cp_async16(sB[s] + 256 * 16, Bg1 + s * 16);
        asm volatile("cp.async.commit_group;\n");
    }

    for (int ch = 0; ch < nch; ch++) {
        asm volatile("cp.async.wait_group %0;\n" :: "n"(STAGES - 2));
        __syncthreads();

        const int buf = ch % STAGES;
        const float4* Ap = As[buf];
        const float4* Bp = Bs[buf];

        // A fragments: 4 x LDS.128 covers both ks steps of the chunk
        float4 A00 = Ap[(wm * 32 + qr) * 4 + qc];
        float4 A01 = Ap[(wm * 32 + 8 + qr) * 4 + qc];
        float4 A10 = Ap[(wm * 32 + 16 + qr) * 4 + qc];
        float4 A11 = Ap[(wm * 32 + 24 + qr) * 4 + qc];

        #pragma unroll
        for (int nt = 0; nt < 8; nt++) {
            float4 bv = Bp[(wn * 64 + nt * 8 + qr) * 4 + qc];
            // ks = 0 (k = qc, qc+4)
            mma_tf32(acc[0][nt][0], acc[0][nt][1], acc[0][nt][2], acc[0][nt][3],
                     __float_as_uint(A00.x), __float_as_uint(A01.x),
                     __float_as_uint(A00.y), __float_as_uint(A01.y),
                     __float_as_uint(bv.x),  __float_as_uint(bv.y));
            mma_tf32(acc[1][nt][0], acc[1][nt][1], acc[1][nt][2], acc[1][nt][3],
                     __float_as_uint(A10.x), __float_as_uint(A11.x),
                     __float_as_uint(A10.y), __float_as_uint(A11.y),
                     __float_as_uint(bv.x),  __float_as_uint(bv.y));
            // ks = 1 (k = qc+8, qc+12)
            mma_tf32(acc[0][nt][0], acc[0][nt][1], acc[0][nt][2], acc[0][nt][3],
                     __float_as_uint(A00.z), __float_as_uint(A01.z),
                     __float_as_uint(A00.w), __float_as_uint(A01.w),
                     __float_as_uint(bv.z),  __float_as_uint(bv.w));
            mma_tf32(acc[1][nt][0], acc[1][nt][1], acc[1][nt][2], acc[1][nt][3],
                     __float_as_uint(A10.z), __float_as_uint(A11.z),
                     __float_as_uint(A10.w), __float_as_uint(A11.w),
                     __float_as_uint(bv.z),  __float_as_uint(bv.w));
        }

        // issue chunk ch+STAGES-1 into the stage read at iter ch-1 (safe:
        // every warp passed this iteration's barrier, so that stage is idle)
        const int nc = ch + STAGES - 1;
        if (nc < nch) {
            const int s = nc % STAGES;
            cp_async16(sA[s],            Ag0 + nc * 16);
            cp_async16(sA[s] + 256 * 16, Ag1 + nc * 16);
            cp_async16(sB[s],            Bg0 + nc * 16);
            cp_async16(sB[s] + 256 * 16, Bg1 + nc * 16);
        }
        asm volatile("cp.async.commit_group;\n");
    }

    // epilogue: bias + store
    #pragma unroll
    for (int f = 0; f < 2; f++) {
        const int r = m0 + wm * 32 + f * 16 + qr;
        float* Crow0 = C + (size_t)r * N + n0 + wn * 64;
        float* Crow1 = C + (size_t)(r + 8) * N + n0 + wn * 64;
        #pragma unroll
        for (int nt = 0; nt < 8; nt++) {
            const int c = nt * 8 + qc * 2;
            float2 bv = *(const float2*)&bias[n0 + wn * 64 + c];
            *(float2*)&Crow0[c] = make_float2(acc[f][nt][0] + bv.x,
                                              acc[f][nt][1] + bv.y);
            *(float2*)&Crow1[c] = make_float2(acc[f][nt][2] + bv.x,
                                              acc[f][nt][3] + bv.y);
        }
    }
}

// ---------------------------------------------------------------------------
// Flash attention on tensor cores (tf32 mma.sync), online softmax.
// (unchanged from R5: register-prefetched K/V tiles)
// ---------------------------------------------------------------------------
__global__ __launch_bounds__(256, 1) void flash_attn_mma(
    const float* __restrict__ qkv, float* __restrict__ out)
{
    constexpr int KS = 68;
    constexpr int VS = 72;
    __shared__ float Ks[64 * KS];
    __shared__ float Vs[64 * VS];

    const int tid  = threadIdx.x;
    const int lane = tid & 31;
    const int w    = tid >> 5;
    const int qr   = lane >> 2;
    const int qc   = lane & 3;
    const int h    = blockIdx.y;
    const int b    = blockIdx.z;
    const int q0   = blockIdx.x * 128;
    const int row0 = w * 16;

    uint32_t Qa[8][4];
    {
        const float* qb    = qkv + ((size_t)(b * Nn + q0)) * D3 + h * DHh;
        const float* qrow0 = qb + (size_t)(row0 + qr) * D3;
        const float* qrow1 = qb + (size_t)(row0 + qr + 8) * D3;
        #pragma unroll
        for (int k = 0; k < 8; k++) {
            Qa[k][0] = f2tf32(qrow0[k * 8 + qc]     * 0.125f);
            Qa[k][1] = f2tf32(qrow1[k * 8 + qc]     * 0.125f);
            Qa[k][2] = f2tf32(qrow0[k * 8 + qc + 4] * 0.125f);
            Qa[k][3] = f2tf32(qrow1[k * 8 + qc + 4] * 0.125f);
        }
    }

    float O[8][4];
    #pragma unroll
    for (int nt = 0; nt < 8; nt++)
        #pragma unroll
        for (int i = 0; i < 4; i++) O[nt][i] = 0.f;
    float mA = -1e30f, mB = -1e30f, lA = 0.f, lB = 0.f;

    const int lrow = tid >> 2;
    const int lseg = (tid & 3) * 16;

    float4 kr[4], vr[4];
    {
        const float* kb = qkv + ((size_t)(b * Nn + lrow)) * D3
                        + Dd + h * DHh + lseg;
        const float* vb = kb + Dd;
        #pragma unroll
        for (int i = 0; i < 4; i++) {
            kr[i] = *(const float4*)(kb + i * 4);
            vr[i] = *(const float4*)(vb + i * 4);
        }
    }

    for (int t = 0; t < Nn / 64; t++) {
        __syncthreads();
        {
            float* kd = &Ks[lrow * KS + lseg];
            float* vd = &Vs[lrow * VS + lseg];
            #pragma unroll
            for (int i = 0; i < 4; i++) {
                kd[i * 4 + 0] = f2tf32f(kr[i].x);
                kd[i * 4 + 1] = f2tf32f(kr[i].y);
                kd[i * 4 + 2] = f2tf32f(kr[i].z);
                kd[i * 4 + 3] = f2tf32f(kr[i].w);
                vd[i * 4 + 0] = f2tf32f(vr[i].x);
                vd[i * 4 + 1] = f2tf32f(vr[i].y);
                vd[i * 4 + 2] = f2tf32f(vr[i].z);
                vd[i * 4 + 3] = f2tf32f(vr[i].w);
            }
        }
        __syncthreads();

        if (t + 1 < Nn / 64) {
            const float* kb = qkv + ((size_t)(b * Nn + (t + 1) * 64 + lrow)) * D3
                            + Dd + h * DHh + lseg;
            const float* vb = kb + Dd;
            #pragma unroll
            for (int i = 0; i < 4; i++) {
                kr[i] = *(const float4*)(kb + i * 4);
                vr[i] = *(const float4*)(vb + i * 4);
            }
        }

        float S[8][4];
        #pragma unroll
        for (int nt = 0; nt < 8; nt++) {
            float c0 = 0.f, c1 = 0.f, c2 = 0.f, c3 = 0.f;
            const float* kbase = &Ks[(nt * 8 + qr) * KS + qc];
            #pragma unroll
            for (int k = 0; k < 8; k++) {
                uint32_t b0 = __float_as_uint(kbase[k * 8]);
                uint32_t b1 = __float_as_uint(kbase[k * 8 + 4]);
                mma_tf32(c0, c1, c2, c3,
                         Qa[k][0], Qa[k][1], Qa[k][2], Qa[k][3], b0, b1);
            }
            S[nt][0] = c0; S[nt][1] = c1; S[nt][2] = c2; S[nt][3] = c3;
        }

        float cmA = -1e30f, cmB = -1e30f;
        #pragma unroll
        for (int nt = 0; nt < 8; nt++) {
            cmA = fmaxf(cmA, fmaxf(S[nt][0], S[nt][1]));
            cmB = fmaxf(cmB, fmaxf(S[nt][2], S[nt][3]));
        }
        cmA = fmaxf(cmA, __shfl_xor_sync(0xffffffffu, cmA, 1));
        cmA = fmaxf(cmA, __shfl_xor_sync(0xffffffffu, cmA, 2));
        cmB = fmaxf(cmB, __shfl_xor_sync(0xffffffffu, cmB, 1));
        cmB = fmaxf(cmB, __shfl_xor_sync(0xffffffffu, cmB, 2));

        const float mnA = fmaxf(mA, cmA), mnB = fmaxf(mB, cmB);
        const float corrA = __expf(mA - mnA), corrB = __expf(mB - mnB);
        #pragma unroll
        for (int nt = 0; nt < 8; nt++) {
            O[nt][0] *= corrA; O[nt][1] *= corrA;
            O[nt][2] *= corrB; O[nt][3] *= corrB;
        }

        float psA = 0.f, psB = 0.f;
        const int quadbase = lane & ~3;
        const int s0l = quadbase | (qc >> 1);
        const int s1l = s0l + 2;
        const bool odd = qc & 1;
        #pragma unroll
        for (int ks = 0; ks < 8; ks++) {
            float p0 = __expf(S[ks][0] - mnA);
            float p1 = __expf(S[ks][1] - mnA);
            float p2 = __expf(S[ks][2] - mnB);
            float p3 = __expf(S[ks][3] - mnB);
            psA += p0 + p1;
            psB += p2 + p3;

            float g00 = __shfl_sync(0xffffffffu, p0, s0l);
            float g01 = __shfl_sync(0xffffffffu, p1, s0l);
            float g20 = __shfl_sync(0xffffffffu, p2, s0l);
            float g21 = __shfl_sync(0xffffffffu, p3, s0l);
            float h00 = __shfl_sync(0xffffffffu, p0, s1l);
            float h01 = __shfl_sync(0xffffffffu, p1, s1l);
            float h20 = __shfl_sync(0xffffffffu, p2, s1l);
            float h21 = __shfl_sync(0xffffffffu, p3, s1l);

            uint32_t a0 = f2tf32(odd ? g01 : g00);
            uint32_t a1 = f2tf32(odd ? g21 : g20);
            uint32_t a2 = f2tf32(odd ? h01 : h00);
            uint32_t a3 = f2tf32(odd ? h21 : h20);

            const float* vbase = &Vs[(ks * 8 + qc) * VS + qr];
            #pragma unroll
            for (int nt = 0; nt < 8; nt++) {
                uint32_t b0 = __float_as_uint(vbase[nt * 8]);
                uint32_t b1 = __float_as_uint(vbase[nt * 8 + 4 * VS]);
                mma_tf32(O[nt][0], O[nt][1], O[nt][2], O[nt][3],
                         a0, a1, a2, a3, b0, b1);
            }
        }
        psA += __shfl_xor_sync(0xffffffffu, psA, 1);
        psA += __shfl_xor_sync(0xffffffffu, psA, 2);
        psB += __shfl_xor_sync(0xffffffffu, psB, 1);
        psB += __shfl_xor_sync(0xffffffffu, psB, 2);
        lA = lA * corrA + psA; mA = mnA;
        lB = lB * corrB + psB; mB = mnB;
    }

    const float invA = 1.f / lA, invB = 1.f / lB;
    float* ob    = out + ((size_t)(b * Nn + q0)) * Dd + h * DHh;
    float* orow0 = ob + (size_t)(row0 + qr) * Dd;
    float* orow1 = ob + (size_t)(row0 + qr + 8) * Dd;
    #pragma unroll
    for (int nt = 0; nt < 8; nt++) {
        int c = nt * 8 + qc * 2;
        *(float2*)&orow0[c] = make_float2(O[nt][0] * invA, O[nt][1] * invA);
        *(float2*)&orow1[c] = make_float2(O[nt][2] * invB, O[nt][3] * invB);
    }
}

// ---------------------------------------------------------------------------
// Host launcher
// ---------------------------------------------------------------------------
extern "C" void kernel_launch(void* const* d_in, const int* in_sizes, int n_in,
                              void* d_out, int out_size)
{
    const float* x     = (const float*)d_in[0];   // [B,N,D]
    const float* W_w   = (const float*)d_in[1];   // [3*H*DH, D]
    const float* W_b   = (const float*)d_in[2];   // [3*H*DH]
    const float* out_w = (const float*)d_in[3];   // [D, H*DH]
    const float* out_b = (const float*)d_in[4];   // [D]

    float *qkv, *attn, *xr, *wwr, *owr, *attnr;
    cudaGetSymbolAddress((void**)&qkv,   g_qkv);
    cudaGetSymbolAddress((void**)&attn,  g_attn);
    cudaGetSymbolAddress((void**)&xr,    g_xr);
    cudaGetSymbolAddress((void**)&wwr,   g_wwr);
    cudaGetSymbolAddress((void**)&owr,   g_owr);
    cudaGetSymbolAddress((void**)&attnr, g_attnr);

    const int M = Bb * Nn;   // 4096

    // pre-pass: round + repack GEMM operands
    {
        int ng;
        ng = M * Dd / 16;
        repack_tf32<<<(ng + 255) / 256, 256>>>(x, xr, ng);
        ng = D3 * Dd / 16;
        repack_tf32<<<(ng + 255) / 256, 256>>>(W_w, wwr, ng);
        ng = Dd * Dd / 16;
        repack_tf32<<<(ng + 255) / 256, 256>>>(out_w, owr, ng);
    }

    // qkv = x @ W_w^T + W_b     [4096, 3072]
    tgemm_v4<<<dim3(D3 / 128, M / 128), 256>>>(xr, wwr, W_b, qkv, M, D3, Dd);

    // attention -> attn [B,N,H*DH]
    flash_attn_mma<<<dim3(Nn / 128, Hh, Bb), 256>>>(qkv, attn);

    // round + repack attn, then out = attn @ out_w^T + out_b   [4096, 1024]
    {
        int ng = M * Dd / 16;
        repack_tf32<<<(ng + 255) / 256, 256>>>(attn, attnr, ng);
    }
    tgemm_v4<<<dim3(Dd / 128, M / 128), 256>>>(attnr, owr, out_b,
                                               (float*)d_out, M, Dd, Dd);
}